// round 6
// baseline (speedup 1.0000x reference)
#include <cuda_runtime.h>
#include <cuda_bf16.h>

// HarmonicMixing, D=1024, strides 2/4/8.
// out[c] = x[c]
//        + sum_o [c % s == 0] * sig(uw[o]) * x[c/s]
//        + sum_o [1 <= c < D/s] * sig(dw[o]) * (sum of x[c*s .. c*s+s-1])
//
// R6: warp-PAIR per row. Each warp holds 4 float4 (16 data regs) -> ~40 regs
// -> 6 CTAs/SM. One named bar.sync(64) per row pair; pairs fully decoupled.
// Warp A (lower half) stages x[0:512] + sums t<128; warp B (upper half)
// produces sums t>=128; B's outputs (c>=512) have no down terms.

#define D 1024
#define THREADS 256
#define PAIRS 4                         // rows per CTA
#define SLAB 1408                       // x[512] | S1[512] | S2[256] | S3[128]

__global__ void __launch_bounds__(THREADS, 6)
harmonic_mixing_kernel(const float* __restrict__ x,
                       const float* __restrict__ up_w,
                       const float* __restrict__ down_w,
                       float* __restrict__ out)
{
    __shared__ __align__(16) float smem[PAIRS][SLAB];

    const int w    = threadIdx.x >> 5;
    const int l    = threadIdx.x & 31;
    const int pair = w >> 1;            // row within CTA
    const int half = w & 1;             // 0 = elements [0,512), 1 = [512,1024)
    const long long row = (long long)blockIdx.x * PAIRS + pair;

    float* sx  = smem[pair];
    float* sS1 = sx  + 512;
    float* sS2 = sS1 + 512;
    float* sS3 = sS2 + 256;

    // Front-batched loads: this warp's iter i covers global group t = 128*half + 32i + l
    const float4* xr = reinterpret_cast<const float4*>(x + row * (long long)D) + half * 128;
    float4 v0 = xr[l];
    float4 v1 = xr[l + 32];
    float4 v2 = xr[l + 64];
    float4 v3 = xr[l + 96];

    // Sigmoids: lanes 0..5 compute, shfl-broadcast (no smem, no extra sync)
    float sig = 0.0f;
    if (l < 6) {
        float wv = (l < 3) ? up_w[l] : down_w[l - 3];
        sig = 1.0f / (1.0f + expf(-wv));
    }
    const float u0 = __shfl_sync(0xffffffffu, sig, 0);
    const float u1 = __shfl_sync(0xffffffffu, sig, 1);
    const float u2 = __shfl_sync(0xffffffffu, sig, 2);
    const float d0 = __shfl_sync(0xffffffffu, sig, 3);
    const float d1 = __shfl_sync(0xffffffffu, sig, 4);
    const float d2 = __shfl_sync(0xffffffffu, sig, 5);

    // Produce: sums for this warp's half; only warp A stages raw x.
    const int tb = half * 128 + l;
#define PRODUCE(i, v)                                                      \
    {                                                                      \
        int t = tb + 32 * (i);                                             \
        if (half == 0) reinterpret_cast<float4*>(sx)[t] = (v);             \
        float _a = (v).x + (v).y, _b = (v).z + (v).w;                      \
        reinterpret_cast<float2*>(sS1)[t] = make_float2(_a, _b);           \
        float _s2 = _a + _b;                                               \
        sS2[t] = _s2;                                                      \
        float _s2n = __shfl_xor_sync(0xffffffffu, _s2, 1);                 \
        if ((l & 1) == 0) sS3[t >> 1] = _s2 + _s2n;                        \
    }
    PRODUCE(0, v0)
    PRODUCE(1, v1)
    PRODUCE(2, v2)
    PRODUCE(3, v3)
#undef PRODUCE

    // Pair-local named barrier (ids 1..4); pairs remain decoupled.
    asm volatile("bar.sync %0, %1;" :: "r"(pair + 1), "n"(64) : "memory");

    float4* outr = reinterpret_cast<float4*>(out + row * (long long)D) + half * 128;

    if (half == 0) {
        // c = 128i + 4l + k   (lower half: all up + all down terms)
#define CONSA(i, v)                                                        \
    {                                                                      \
        float r0 = (v).x, r1 = (v).y, r2 = (v).z, r3 = (v).w;              \
        float2 xu = reinterpret_cast<const float2*>(sx)[32 * (i) + l];     \
        r0 += u0 * xu.x;                   /* stride 2, k=0 */             \
        r2 += u0 * xu.y;                   /* stride 2, k=2 */             \
        r0 += u1 * sx[32 * (i) + l];       /* stride 4, k=0 */             \
        if ((l & 1) == 0) r0 += u2 * sx[16 * (i) + (l >> 1)]; /* stride 8*/\
        {                                                                  \
            float4 a = reinterpret_cast<const float4*>(sS1)[32 * (i) + l]; \
            r0 += d0 * a.x; r1 += d0 * a.y; r2 += d0 * a.z; r3 += d0 * a.w;\
        }                                                                  \
        if ((i) < 2) {                                                     \
            float4 a = reinterpret_cast<const float4*>(sS2)[32 * (i) + l]; \
            r0 += d1 * a.x; r1 += d1 * a.y; r2 += d1 * a.z; r3 += d1 * a.w;\
        }                                                                  \
        if ((i) == 0) {                                                    \
            float4 a = reinterpret_cast<const float4*>(sS3)[l];            \
            r0 += d2 * a.x; r1 += d2 * a.y; r2 += d2 * a.z; r3 += d2 * a.w;\
            if (l == 0)  /* c = 0 is not a down target */                  \
                r0 -= d0 * sS1[0] + d1 * sS2[0] + d2 * sS3[0];             \
        }                                                                  \
        outr[32 * (i) + l] = make_float4(r0, r1, r2, r3);                  \
    }
        CONSA(0, v0)
        CONSA(1, v1)
        CONSA(2, v2)
        CONSA(3, v3)
#undef CONSA
    } else {
        // c = 512 + 128i + 4l + k   (upper half: up terms only, no down)
#define CONSB(i, v)                                                        \
    {                                                                      \
        float r0 = (v).x, r1 = (v).y, r2 = (v).z, r3 = (v).w;              \
        float2 xu = reinterpret_cast<const float2*>(sx)[128 + 32 * (i) + l];\
        r0 += u0 * xu.x;                         /* x[256+64i+2l]   */     \
        r2 += u0 * xu.y;                         /* x[256+64i+2l+1] */     \
        r0 += u1 * sx[128 + 32 * (i) + l];       /* x[128+32i+l]    */     \
        if ((l & 1) == 0) r0 += u2 * sx[64 + 16 * (i) + (l >> 1)];         \
        outr[32 * (i) + l] = make_float4(r0, r1, r2, r3);                  \
    }
        CONSB(0, v0)
        CONSB(1, v1)
        CONSB(2, v2)
        CONSB(3, v3)
#undef CONSB
    }
}

extern "C" void kernel_launch(void* const* d_in, const int* in_sizes, int n_in,
                              void* d_out, int out_size)
{
    const float* x  = (const float*)d_in[0];
    const float* uw = (const float*)d_in[1];
    const float* dw = (const float*)d_in[2];
    float* out = (float*)d_out;

    const int rows = in_sizes[0] / D;        // 32768
    const int grid = rows / PAIRS;           // 8192
    harmonic_mixing_kernel<<<grid, THREADS>>>(x, uw, dw, out);
}